// round 4
// baseline (speedup 1.0000x reference)
#include <cuda_runtime.h>
#include <math.h>

#define NN 16384
#define EE 524288
#define HH 128
#define CAP 128   // bucket capacity per row

// ---------------- device scratch (static; no allocations) ----------------
__device__ float g_Q[NN * HH], g_K[NN * HH], g_V[NN * HH];
__device__ float g_h1[NN * HH], g_y[NN * HH];
__device__ float g_t1[NN * 2 * HH];
__device__ float g_w1t[HH * 2 * HH];    // bn1-folded W1
__device__ float g_b1t[2 * HH];         // bn1-folded b1
__device__ int   g_cnt[NN];
__device__ int   g_bd[NN * CAP];     // bucketed dst per src row
__device__ float g_bs[NN * CAP];     // bucketed edge bias per src row
__device__ float g_sv[HH], g_svq[HH], g_s1[HH], g_ss1[HH], g_s2[HH], g_ss2[HH];
__device__ float g_a1[HH], g_c1[HH], g_a2[HH], g_c2[HH];
__device__ int   g_ctr[3];
__device__ int   g_is64;

// edge_index may arrive as int64 (per reference) or int32 (JAX without x64).
__device__ __forceinline__ int edge_src(const void* p, int e) {
    return g_is64 ? (int)((const long long*)p)[e] : ((const int*)p)[e];
}
__device__ __forceinline__ int edge_dst(const void* p, int e) {
    return g_is64 ? (int)((const long long*)p)[(size_t)EE + e] : ((const int*)p)[(size_t)EE + e];
}

// ---------------- f32x2 packed FMA helpers (sm_100+) ----------------
__device__ __forceinline__ void ffma2(unsigned long long& d, unsigned long long a,
                                      unsigned long long b) {
    asm volatile("fma.rn.f32x2 %0, %1, %2, %0;" : "+l"(d) : "l"(a), "l"(b));
}
__device__ __forceinline__ unsigned long long pk2(float lo, float hi) {
    unsigned long long r;
    asm("mov.b64 %0, {%1, %2};" : "=l"(r) : "f"(lo), "f"(hi));
    return r;
}
__device__ __forceinline__ void upk2(unsigned long long v, float& lo, float& hi) {
    asm("mov.b64 {%0, %1}, %2;" : "=f"(lo), "=f"(hi) : "l"(v));
}

// ---------------- cp.async helpers ----------------
__device__ __forceinline__ void cpa16(void* s, const void* g) {
    unsigned sa = (unsigned)__cvta_generic_to_shared(s);
    asm volatile("cp.async.ca.shared.global [%0], [%1], 16;" :: "r"(sa), "l"(g));
}
#define CP_COMMIT()  asm volatile("cp.async.commit_group;")
#define CP_WAIT(n)   asm volatile("cp.async.wait_group %0;" :: "n"(n))

// ---------------- init ----------------
__global__ void k_init(const void* ei) {
    int t = blockIdx.x * blockDim.x + threadIdx.x;
    if (t < NN) g_cnt[t] = 0;
    if (t < HH) {
        g_sv[t] = 0.f; g_svq[t] = 0.f;
        g_s1[t] = 0.f; g_ss1[t] = 0.f;
        g_s2[t] = 0.f; g_ss2[t] = 0.f;
    }
    if (t < 3) g_ctr[t] = 0;
    if (t == 0) {
        const unsigned* u = (const unsigned*)ei;
        int is64 = 1;
        for (int j = 1; j < 256; j += 2) if (u[j] != 0u) { is64 = 0; break; }
        g_is64 = is64;
    }
}

// ---------------- scatter: per-edge bucket write (dst, edge-bias) ----------------
__global__ void k_scatter(const void* __restrict__ ei, const float* __restrict__ ea,
                          const float* __restrict__ We, const float* __restrict__ be) {
    __shared__ float sW[16];
    __shared__ float sbe;
    if (threadIdx.x < 16) sW[threadIdx.x] = We[threadIdx.x];
    if (threadIdx.x == 0) sbe = be[0];
    __syncthreads();
    int e = blockIdx.x * 256 + threadIdx.x;
    int src = edge_src(ei, e), dst = edge_dst(ei, e);
    const float4* a4 = (const float4*)(ea + (size_t)e * 16);
    float eb = sbe;
#pragma unroll
    for (int q = 0; q < 4; q++) {
        float4 v = a4[q];
        eb += v.x * sW[4 * q] + v.y * sW[4 * q + 1] + v.z * sW[4 * q + 2] + v.w * sW[4 * q + 3];
    }
    int pos = atomicAdd(&g_cnt[src], 1);
    if (pos < CAP) {
        g_bd[src * CAP + pos] = dst;
        g_bs[src * CAP + pos] = eb;
    }
}

// ---------------- fp32 GEMM: 64x128 tile, 4x8/thread, f32x2, cp.async 2-stage ----------------
// blockIdx.z selects among up to 3 (W, bias, C) triples (fused QKV).
// useRes: add bn1(h1) residual in epilogue (M==HH).
__global__ void __launch_bounds__(256, 3) k_mm(
    const float* __restrict__ A,
    const float* __restrict__ W0, const float* __restrict__ W1, const float* __restrict__ W2,
    const float* __restrict__ b0, const float* __restrict__ b1, const float* __restrict__ b2,
    float* __restrict__ C0, float* __restrict__ C1, float* __restrict__ C2,
    int K, int M, int relu, int useRes)
{
    const float* W    = (blockIdx.z == 0) ? W0 : (blockIdx.z == 1) ? W1 : W2;
    const float* bias = (blockIdx.z == 0) ? b0 : (blockIdx.z == 1) ? b1 : b2;
    float*       C    = (blockIdx.z == 0) ? C0 : (blockIdx.z == 1) ? C1 : C2;

    extern __shared__ float smem[];
    // As: 2 stages of [64][36], Bs: 2 stages of [32][132]
    float* AsBase = smem;                      // 2*64*36 = 4608 floats
    float* BsBase = smem + 2 * 64 * 36;        // 2*32*132 = 8448 floats

    int tid = threadIdx.x;
    int tx = tid & 15, ty = tid >> 4;
    int row0 = blockIdx.y * 64, col0 = blockIdx.x * 128;

    const int NT = K >> 5;   // K/32 tiles

    // per-thread load coordinates
    int am[2], ak[2], bk[4], bj[4];
#pragma unroll
    for (int q = 0; q < 2; q++) { int fid = tid + q * 256; am[q] = fid >> 3; ak[q] = (fid & 7) << 2; }
#pragma unroll
    for (int q = 0; q < 4; q++) { int fid = tid + q * 256; bk[q] = fid >> 5; bj[q] = (fid & 31) << 2; }

    // preload tile 0 into stage 0
#pragma unroll
    for (int q = 0; q < 2; q++)
        cpa16(&AsBase[am[q] * 36 + ak[q]], &A[(size_t)(row0 + am[q]) * K + ak[q]]);
#pragma unroll
    for (int q = 0; q < 4; q++)
        cpa16(&BsBase[bk[q] * 132 + bj[q]], &W[(size_t)bk[q] * M + col0 + bj[q]]);
    CP_COMMIT();

    unsigned long long acc[4][4];
#pragma unroll
    for (int i = 0; i < 4; i++)
#pragma unroll
        for (int j = 0; j < 4; j++) acc[i][j] = 0ULL;

    for (int t = 0; t < NT; t++) {
        int cur = t & 1;
        if (t + 1 < NT) {
            int nxt = (t + 1) & 1;
            int kt = (t + 1) << 5;
            float* Asn = AsBase + nxt * 64 * 36;
            float* Bsn = BsBase + nxt * 32 * 132;
#pragma unroll
            for (int q = 0; q < 2; q++)
                cpa16(&Asn[am[q] * 36 + ak[q]], &A[(size_t)(row0 + am[q]) * K + kt + ak[q]]);
#pragma unroll
            for (int q = 0; q < 4; q++)
                cpa16(&Bsn[bk[q] * 132 + bj[q]], &W[(size_t)(kt + bk[q]) * M + col0 + bj[q]]);
            CP_COMMIT();
            CP_WAIT(1);
        } else {
            CP_WAIT(0);
        }
        __syncthreads();

        const float* As = AsBase + cur * 64 * 36;
        const float* Bs = BsBase + cur * 32 * 132;
#pragma unroll
        for (int k = 0; k < 32; k++) {
            float4 v0 = *(const float4*)&Bs[k * 132 + tx * 8];
            float4 v1 = *(const float4*)&Bs[k * 132 + tx * 8 + 4];
            unsigned long long bb[4] = {pk2(v0.x, v0.y), pk2(v0.z, v0.w),
                                        pk2(v1.x, v1.y), pk2(v1.z, v1.w)};
#pragma unroll
            for (int i = 0; i < 4; i++) {
                float a = As[(ty * 4 + i) * 36 + k];
                unsigned long long aa = pk2(a, a);
#pragma unroll
                for (int j = 0; j < 4; j++) ffma2(acc[i][j], aa, bb[j]);
            }
        }
        __syncthreads();
    }

    // epilogue
#pragma unroll
    for (int i = 0; i < 4; i++) {
        int r = row0 + ty * 4 + i;
        float o[8];
#pragma unroll
        for (int j = 0; j < 4; j++) upk2(acc[i][j], o[2 * j], o[2 * j + 1]);
#pragma unroll
        for (int j = 0; j < 8; j++) {
            int cc = col0 + tx * 8 + j;
            float v = o[j] + bias[cc];
            if (relu) v = fmaxf(v, 0.f);
            if (useRes) v += g_h1[(size_t)r * HH + cc] * g_a1[cc] + g_c1[cc];
            o[j] = v;
        }
        float4* dst = (float4*)&C[(size_t)r * M + col0 + tx * 8];
        dst[0] = make_float4(o[0], o[1], o[2], o[3]);
        dst[1] = make_float4(o[4], o[5], o[6], o[7]);
    }
}

// ---------------- column sum + sum-of-squares over [NN, HH] + BN finalize ----------------
// 512 blocks x 256 threads; block handles 32 rows; lane-coalesced column reads.
// Last finished block computes the BN affine (sel 1 -> a1/c1, sel 2 -> a2/c2).
__global__ void k_colreduce(const float* __restrict__ A, int sel,
                            const float* __restrict__ g, const float* __restrict__ b) {
    int col = threadIdx.x & 127;
    int half = threadIdx.x >> 7;
    int r0 = blockIdx.x * 32 + half * 16;
    float s = 0.f, q = 0.f;
#pragma unroll 4
    for (int r = r0; r < r0 + 16; r++) {
        float v = A[(size_t)r * HH + col];
        s += v; q += v * v;
    }
    float* ps = (sel == 0) ? g_sv : (sel == 1) ? g_s1 : g_s2;
    float* pq = (sel == 0) ? g_svq : (sel == 1) ? g_ss1 : g_ss2;
    atomicAdd(&ps[col], s);
    atomicAdd(&pq[col], q);
    if (sel == 0) return;
    __threadfence();
    __shared__ int isLast;
    if (threadIdx.x == 0) isLast = (atomicAdd(&g_ctr[sel], 1) == (int)gridDim.x - 1);
    __syncthreads();
    if (isLast && threadIdx.x < 128) {
        int h = threadIdx.x;
        float mu = ps[h] * (1.0f / NN);
        float var = pq[h] * (1.0f / NN) - mu * mu;
        float a = g[h] * rsqrtf(var + 1e-5f);
        float c = b[h] - mu * a;
        if (sel == 1) { g_a1[h] = a; g_c1[h] = c; }
        else          { g_a2[h] = a; g_c2[h] = c; }
    }
}

// ---------------- fold bn1 into FFN1 weights: W1' = diag(a1) W1, b1' = b1 + c1^T W1 ----------------
__global__ void k_prep1(const float* __restrict__ W1, const float* __restrict__ b1) {
    int j = blockIdx.x;      // 0..255
    int k = threadIdx.x;     // 0..127
    float a = g_a1[k], c = g_c1[k];
    float w = W1[k * 256 + j];
    g_w1t[k * 256 + j] = a * w;
    __shared__ float red[128];
    red[k] = c * w;
    __syncthreads();
    for (int off = 64; off; off >>= 1) {
        if (k < off) red[k] += red[k + off];
        __syncthreads();
    }
    if (k == 0) g_b1t[j] = b1[j] + red[0];
}

// ---------------- per-row: scores + dedup + sparse softmax aggregation ----------------
// attn@V row i = (S_V + sum_unique (exp(s)-1)*V[dst]) / (N + sum_unique (exp(s)-1))
__global__ void k_rows(const float* __restrict__ x) {
    int i = blockIdx.x;
    int tid = threadIdx.x;
    int wid = tid >> 5, lane = tid & 31;
    __shared__ float qrow[HH];
    __shared__ int   sdst[CAP];
    __shared__ float ss[CAP];      // edge bias, then leaky score
    __shared__ float sw[CAP];      // exp(s)-1 weight (0 for non-leaders)

    qrow[tid] = g_Q[(size_t)i * HH + tid];
    int d = g_cnt[i];
    if (d > CAP) d = CAP;
    if (tid < d) {
        sdst[tid] = g_bd[i * CAP + tid];
        ss[tid]   = g_bs[i * CAP + tid];
    }
    __syncthreads();

    // scores: one warp per entry, 128-dim dot over smem Q and L2 K
    for (int j = wid; j < d; j += 4) {
        int dj = sdst[j];
        float4 kv = ((const float4*)(g_K + (size_t)dj * HH))[lane];
        float4 qv = ((const float4*)qrow)[lane];
        float p = kv.x * qv.x + kv.y * qv.y + kv.z * qv.z + kv.w * qv.w;
#pragma unroll
        for (int off = 16; off; off >>= 1) p += __shfl_down_sync(0xffffffffu, p, off);
        if (lane == 0) {
            float s = p + ss[j];
            ss[j] = (s >= 0.f) ? s : 0.01f * s;   // leaky relu
        }
    }
    __syncthreads();

    // dedup: duplicate (i,dst) scores sum inside the exp; leader = lowest index
    if (tid < d) {
        int dj = sdst[tid];
        float s = 0.f;
        bool lead = true;
        for (int t = 0; t < d; t++) {
            if (sdst[t] == dj) {
                if (t < tid) { lead = false; break; }
                s += ss[t];
            }
        }
        sw[tid] = lead ? (expf(s) - 1.0f) : 0.0f;
    }
    __syncthreads();

    float acc = 0.f, wsum = 0.f;
    for (int t = 0; t < d; t++) {
        float w = sw[t];
        if (w != 0.f) {
            acc += w * g_V[(size_t)sdst[t] * HH + tid];
            wsum += w;
        }
    }
    float Z = (float)NN + wsum;
    float xn = (g_sv[tid] + acc) / Z;
    g_h1[(size_t)i * HH + tid] = x[(size_t)i * HH + tid] + xn;
}

// ---------------- final bn2 apply ----------------
__global__ void k_apply(float* __restrict__ out) {
    int t = blockIdx.x * 256 + threadIdx.x;
    int h = t & 127;
    out[t] = g_y[t] * g_a2[h] + g_c2[h];
}

// ---------------- launch ----------------
extern "C" void kernel_launch(void* const* d_in, const int* in_sizes, int n_in,
                              void* d_out, int out_size) {
    (void)in_sizes; (void)n_in; (void)out_size;
    const float* x   = (const float*)d_in[0];
    const void*  ei  = d_in[1];
    const float* ea  = (const float*)d_in[2];
    const float* Wq  = (const float*)d_in[3];
    const float* bq  = (const float*)d_in[4];
    const float* Wk  = (const float*)d_in[5];
    const float* bk  = (const float*)d_in[6];
    const float* Wv  = (const float*)d_in[7];
    const float* bv  = (const float*)d_in[8];
    const float* We  = (const float*)d_in[9];
    const float* be  = (const float*)d_in[10];
    const float* bn1g = (const float*)d_in[11];
    const float* bn1b = (const float*)d_in[12];
    const float* W1  = (const float*)d_in[13];
    const float* b1  = (const float*)d_in[14];
    const float* W2  = (const float*)d_in[15];
    const float* b2  = (const float*)d_in[16];
    const float* bn2g = (const float*)d_in[17];
    const float* bn2b = (const float*)d_in[18];
    float* out = (float*)d_out;

    float *pQ, *pK, *pV, *ph1, *pt1, *py, *pw1t, *pb1t;
    cudaGetSymbolAddress((void**)&pQ,   g_Q);
    cudaGetSymbolAddress((void**)&pK,   g_K);
    cudaGetSymbolAddress((void**)&pV,   g_V);
    cudaGetSymbolAddress((void**)&ph1,  g_h1);
    cudaGetSymbolAddress((void**)&pt1,  g_t1);
    cudaGetSymbolAddress((void**)&py,   g_y);
    cudaGetSymbolAddress((void**)&pw1t, g_w1t);
    cudaGetSymbolAddress((void**)&pb1t, g_b1t);

    const int SMEM = (2 * 64 * 36 + 2 * 32 * 132) * 4;   // 52224 B
    static int attrSet = 0;
    if (!attrSet) {
        cudaFuncSetAttribute(k_mm, cudaFuncAttributeMaxDynamicSharedMemorySize, SMEM);
        attrSet = 1;
    }

    k_init<<<64, 256>>>(ei);
    k_scatter<<<EE / 256, 256>>>(ei, ea, We, be);

    // fused QKV: grid.z selects weight/bias/output
    dim3 gqkv(1, NN / 64, 3);
    k_mm<<<gqkv, 256, SMEM>>>(x, Wq, Wk, Wv, bq, bk, bv, pQ, pK, pV, HH, HH, 0, 0);

    k_colreduce<<<512, 256>>>(pV, 0, bn1g, bn1b);   // S_V column sums (no finalize)

    k_rows<<<NN, 128>>>(x);

    k_colreduce<<<512, 256>>>(ph1, 1, bn1g, bn1b);  // bn1 stats + a1/c1 finalize
    k_prep1<<<256, 128>>>(W1, b1);

    // FFN1: [NN,128] @ folded [128,256], relu
    dim3 gf1(2 * HH / 128, NN / 64, 1);
    k_mm<<<gf1, 256, SMEM>>>(ph1, pw1t, pw1t, pw1t, pb1t, pb1t, pb1t,
                             pt1, pt1, pt1, HH, 2 * HH, 1, 0);
    // FFN2: [NN,256] @ [256,128] + bn1(h1) residual
    dim3 gf2(HH / 128, NN / 64, 1);
    k_mm<<<gf2, 256, SMEM>>>(pt1, W2, W2, W2, b2, b2, b2,
                             py, py, py, 2 * HH, HH, 0, 1);

    k_colreduce<<<512, 256>>>(py, 2, bn2g, bn2b);   // bn2 stats + a2/c2 finalize
    k_apply<<<NN * HH / 256, 256>>>(out);
}

// round 8
// speedup vs baseline: 1.0905x; 1.0905x over previous
#include <cuda_runtime.h>
#include <math.h>

#define NN 16384
#define EE 524288
#define HH 128
#define CAP 128   // bucket capacity per row

// ---------------- device scratch (static; no allocations) ----------------
__device__ float g_Q[NN * HH], g_K[NN * HH], g_V[NN * HH];
__device__ float g_h1[NN * HH], g_y[NN * HH];
__device__ float g_t1[NN * 2 * HH];
__device__ float g_w1t[HH * 2 * HH];    // bn1-folded W1
__device__ float g_b1t[2 * HH];         // bn1-folded b1
__device__ int   g_cnt[NN];
__device__ int   g_bd[NN * CAP];     // bucketed dst per src row
__device__ float g_bs[NN * CAP];     // bucketed edge bias per src row
__device__ float g_sv[HH], g_s1[HH], g_ss1[HH], g_s2[HH], g_ss2[HH];
__device__ float g_a1[HH], g_c1[HH], g_a2[HH], g_c2[HH];
__device__ int   g_ctr[3];
__device__ int   g_is64;

// edge_index may arrive as int64 (per reference) or int32 (JAX without x64).
__device__ __forceinline__ int edge_src(const void* p, int e) {
    return g_is64 ? (int)((const long long*)p)[e] : ((const int*)p)[e];
}
__device__ __forceinline__ int edge_dst(const void* p, int e) {
    return g_is64 ? (int)((const long long*)p)[(size_t)EE + e] : ((const int*)p)[(size_t)EE + e];
}

// ---------------- f32x2 packed FMA helpers (sm_100+) ----------------
__device__ __forceinline__ void ffma2(unsigned long long& d, unsigned long long a,
                                      unsigned long long b) {
    asm volatile("fma.rn.f32x2 %0, %1, %2, %0;" : "+l"(d) : "l"(a), "l"(b));
}
__device__ __forceinline__ unsigned long long pk2(float lo, float hi) {
    unsigned long long r;
    asm("mov.b64 %0, {%1, %2};" : "=l"(r) : "f"(lo), "f"(hi));
    return r;
}
__device__ __forceinline__ void upk2(unsigned long long v, float& lo, float& hi) {
    asm("mov.b64 {%0, %1}, %2;" : "=f"(lo), "=f"(hi) : "l"(v));
}

// ---------------- cp.async helpers ----------------
__device__ __forceinline__ void cpa16(void* s, const void* g) {
    unsigned sa = (unsigned)__cvta_generic_to_shared(s);
    asm volatile("cp.async.ca.shared.global [%0], [%1], 16;" :: "r"(sa), "l"(g));
}
#define CP_COMMIT()  asm volatile("cp.async.commit_group;")
#define CP_WAIT(n)   asm volatile("cp.async.wait_group %0;" :: "n"(n))

// ---------------- init ----------------
__global__ void k_init(const void* ei) {
    int t = blockIdx.x * blockDim.x + threadIdx.x;
    if (t < NN) g_cnt[t] = 0;
    if (t < HH) {
        g_sv[t] = 0.f;
        g_s1[t] = 0.f; g_ss1[t] = 0.f;
        g_s2[t] = 0.f; g_ss2[t] = 0.f;
    }
    if (t < 3) g_ctr[t] = 0;
    if (t == 0) {
        const unsigned* u = (const unsigned*)ei;
        int is64 = 1;
        for (int j = 1; j < 256; j += 2) if (u[j] != 0u) { is64 = 0; break; }
        g_is64 = is64;
    }
}

// ---------------- scatter: per-edge bucket write (dst, edge-bias) ----------------
__global__ void k_scatter(const void* __restrict__ ei, const float* __restrict__ ea,
                          const float* __restrict__ We, const float* __restrict__ be) {
    __shared__ float sW[16];
    __shared__ float sbe;
    if (threadIdx.x < 16) sW[threadIdx.x] = We[threadIdx.x];
    if (threadIdx.x == 0) sbe = be[0];
    __syncthreads();
    int e = blockIdx.x * 256 + threadIdx.x;
    int src = edge_src(ei, e), dst = edge_dst(ei, e);
    const float4* a4 = (const float4*)(ea + (size_t)e * 16);
    float eb = sbe;
#pragma unroll
    for (int q = 0; q < 4; q++) {
        float4 v = a4[q];
        eb += v.x * sW[4 * q] + v.y * sW[4 * q + 1] + v.z * sW[4 * q + 2] + v.w * sW[4 * q + 3];
    }
    int pos = atomicAdd(&g_cnt[src], 1);
    if (pos < CAP) {
        g_bd[src * CAP + pos] = dst;
        g_bs[src * CAP + pos] = eb;
    }
}

// ---------------- fp32 GEMM: 64x128 tile, 4x8/thread, f32x2, cp.async 2-stage ----------------
// blockIdx.z selects among up to 3 (W, bias, C) triples (fused QKV).
// useRes: add bn1(h1) residual in epilogue (M==HH).
// colsum_z >= 0: blocks with blockIdx.z == colsum_z accumulate column sums of C
//   (sel 0 -> g_sv only; sel 2 -> g_s2/g_ss2 + last-block bn2 finalize). Requires gridDim.x==1.
__global__ void __launch_bounds__(256, 3) k_mm(
    const float* __restrict__ A,
    const float* __restrict__ W0, const float* __restrict__ W1, const float* __restrict__ W2,
    const float* __restrict__ b0, const float* __restrict__ b1, const float* __restrict__ b2,
    float* __restrict__ C0, float* __restrict__ C1, float* __restrict__ C2,
    int K, int M, int relu, int useRes,
    int colsum_z, int sel, const float* __restrict__ bng, const float* __restrict__ bnb)
{
    const float* W    = (blockIdx.z == 0) ? W0 : (blockIdx.z == 1) ? W1 : W2;
    const float* bias = (blockIdx.z == 0) ? b0 : (blockIdx.z == 1) ? b1 : b2;
    float*       C    = (blockIdx.z == 0) ? C0 : (blockIdx.z == 1) ? C1 : C2;

    extern __shared__ float smem[];
    float* AsBase = smem;                      // 2*64*36 = 4608 floats
    float* BsBase = smem + 2 * 64 * 36;        // 2*32*132 = 8448 floats

    int tid = threadIdx.x;
    int tx = tid & 15, ty = tid >> 4;
    int row0 = blockIdx.y * 64, col0 = blockIdx.x * 128;

    const int NT = K >> 5;   // K/32 tiles

    int am[2], ak[2], bk[4], bj[4];
#pragma unroll
    for (int q = 0; q < 2; q++) { int fid = tid + q * 256; am[q] = fid >> 3; ak[q] = (fid & 7) << 2; }
#pragma unroll
    for (int q = 0; q < 4; q++) { int fid = tid + q * 256; bk[q] = fid >> 5; bj[q] = (fid & 31) << 2; }

    // preload tile 0 into stage 0
#pragma unroll
    for (int q = 0; q < 2; q++)
        cpa16(&AsBase[am[q] * 36 + ak[q]], &A[(size_t)(row0 + am[q]) * K + ak[q]]);
#pragma unroll
    for (int q = 0; q < 4; q++)
        cpa16(&BsBase[bk[q] * 132 + bj[q]], &W[(size_t)bk[q] * M + col0 + bj[q]]);
    CP_COMMIT();

    unsigned long long acc[4][4];
#pragma unroll
    for (int i = 0; i < 4; i++)
#pragma unroll
        for (int j = 0; j < 4; j++) acc[i][j] = 0ULL;

    for (int t = 0; t < NT; t++) {
        int cur = t & 1;
        if (t + 1 < NT) {
            int nxt = (t + 1) & 1;
            int kt = (t + 1) << 5;
            float* Asn = AsBase + nxt * 64 * 36;
            float* Bsn = BsBase + nxt * 32 * 132;
#pragma unroll
            for (int q = 0; q < 2; q++)
                cpa16(&Asn[am[q] * 36 + ak[q]], &A[(size_t)(row0 + am[q]) * K + kt + ak[q]]);
#pragma unroll
            for (int q = 0; q < 4; q++)
                cpa16(&Bsn[bk[q] * 132 + bj[q]], &W[(size_t)(kt + bk[q]) * M + col0 + bj[q]]);
            CP_COMMIT();
            CP_WAIT(1);
        } else {
            CP_WAIT(0);
        }
        __syncthreads();

        const float* As = AsBase + cur * 64 * 36;
        const float* Bs = BsBase + cur * 32 * 132;
#pragma unroll
        for (int k = 0; k < 32; k++) {
            float4 v0 = *(const float4*)&Bs[k * 132 + tx * 8];
            float4 v1 = *(const float4*)&Bs[k * 132 + tx * 8 + 4];
            unsigned long long bb[4] = {pk2(v0.x, v0.y), pk2(v0.z, v0.w),
                                        pk2(v1.x, v1.y), pk2(v1.z, v1.w)};
#pragma unroll
            for (int i = 0; i < 4; i++) {
                float a = As[(ty * 4 + i) * 36 + k];
                unsigned long long aa = pk2(a, a);
#pragma unroll
                for (int j = 0; j < 4; j++) ffma2(acc[i][j], aa, bb[j]);
            }
        }
        __syncthreads();
    }

    // epilogue
    bool doCS = (colsum_z == (int)blockIdx.z);
    float csum[8], csq[8];
#pragma unroll
    for (int j = 0; j < 8; j++) { csum[j] = 0.f; csq[j] = 0.f; }

#pragma unroll
    for (int i = 0; i < 4; i++) {
        int r = row0 + ty * 4 + i;
        float o[8];
#pragma unroll
        for (int j = 0; j < 4; j++) upk2(acc[i][j], o[2 * j], o[2 * j + 1]);
#pragma unroll
        for (int j = 0; j < 8; j++) {
            int cc = col0 + tx * 8 + j;
            float v = o[j] + bias[cc];
            if (relu) v = fmaxf(v, 0.f);
            if (useRes) v += g_h1[(size_t)r * HH + cc] * g_a1[cc] + g_c1[cc];
            o[j] = v;
            if (doCS) { csum[j] += v; csq[j] += v * v; }
        }
        float4* dst = (float4*)&C[(size_t)r * M + col0 + tx * 8];
        dst[0] = make_float4(o[0], o[1], o[2], o[3]);
        dst[1] = make_float4(o[4], o[5], o[6], o[7]);
    }

    if (doCS) {
        float* red  = smem;             // [16][128]
        float* redq = smem + 16 * 128;  // [16][128]
#pragma unroll
        for (int j = 0; j < 8; j++) {
            red [ty * 128 + tx * 8 + j] = csum[j];
            redq[ty * 128 + tx * 8 + j] = csq[j];
        }
        __syncthreads();
        if (tid < 128) {
            float s = 0.f, q = 0.f;
#pragma unroll
            for (int t = 0; t < 16; t++) { s += red[t * 128 + tid]; q += redq[t * 128 + tid]; }
            if (sel == 0) {
                atomicAdd(&g_sv[tid], s);
            } else {
                atomicAdd(&g_s2[tid], s);
                atomicAdd(&g_ss2[tid], q);
            }
        }
        if (sel == 2) {
            __threadfence();
            __syncthreads();
            __shared__ int isLast;
            if (tid == 0)
                isLast = (atomicAdd(&g_ctr[2], 1) == (int)(gridDim.x * gridDim.y) - 1);
            __syncthreads();
            if (isLast && tid < 128) {
                int h = tid;
                float mu = g_s2[h] * (1.0f / NN);
                float var = g_ss2[h] * (1.0f / NN) - mu * mu;
                float a = bng[h] * rsqrtf(var + 1e-5f);
                g_a2[h] = a;
                g_c2[h] = bnb[h] - mu * a;
            }
        }
    }
}

// ---------------- h1 column stats + bn1 finalize ----------------
// 128 blocks x 512 threads; block covers 128 rows; 1 atomic per column per block.
__global__ void k_cr1(const float* __restrict__ A,
                      const float* __restrict__ g, const float* __restrict__ b) {
    int col = threadIdx.x & 127;
    int rr = threadIdx.x >> 7;          // 0..3
    int r0 = blockIdx.x * 128;
    float s = 0.f, q = 0.f;
#pragma unroll 8
    for (int r = rr; r < 128; r += 4) {
        float v = A[(size_t)(r0 + r) * HH + col];
        s += v; q += v * v;
    }
    __shared__ float rs[4][128], rq[4][128];
    rs[rr][col] = s; rq[rr][col] = q;
    __syncthreads();
    if (threadIdx.x < 128) {
        s = rs[0][col] + rs[1][col] + rs[2][col] + rs[3][col];
        q = rq[0][col] + rq[1][col] + rq[2][col] + rq[3][col];
        atomicAdd(&g_s1[col], s);
        atomicAdd(&g_ss1[col], q);
    }
    __threadfence();
    __syncthreads();
    __shared__ int isLast;
    if (threadIdx.x == 0) isLast = (atomicAdd(&g_ctr[1], 1) == (int)gridDim.x - 1);
    __syncthreads();
    if (isLast && threadIdx.x < 128) {
        int h = threadIdx.x;
        float mu = g_s1[h] * (1.0f / NN);
        float var = g_ss1[h] * (1.0f / NN) - mu * mu;
        float a = g[h] * rsqrtf(var + 1e-5f);
        g_a1[h] = a;
        g_c1[h] = b[h] - mu * a;
    }
}

// ---------------- fold bn1 into FFN1 weights: W1' = diag(a1) W1, b1' = b1 + c1^T W1 ----------------
__global__ void k_prep1(const float* __restrict__ W1, const float* __restrict__ b1) {
    int j = blockIdx.x;      // 0..255
    int k = threadIdx.x;     // 0..127
    float a = g_a1[k], c = g_c1[k];
    float w = W1[k * 256 + j];
    g_w1t[k * 256 + j] = a * w;
    __shared__ float red[128];
    red[k] = c * w;
    __syncthreads();
    for (int off = 64; off; off >>= 1) {
        if (k < off) red[k] += red[k + off];
        __syncthreads();
    }
    if (k == 0) g_b1t[j] = b1[j] + red[0];
}

// ---------------- per-row: scores + dedup + sparse softmax aggregation ----------------
// attn@V row i = (S_V + sum_unique (exp(s)-1)*V[dst]) / (N + sum_unique (exp(s)-1))
__global__ void k_rows(const float* __restrict__ x) {
    int i = blockIdx.x;
    int tid = threadIdx.x;
    int wid = tid >> 5, lane = tid & 31;
    __shared__ float qrow[HH];
    __shared__ int   sdst[CAP];
    __shared__ float ss[CAP];      // edge bias, then leaky score
    __shared__ float sw[CAP];      // exp(s)-1 weight (0 for non-leaders)

    qrow[tid] = g_Q[(size_t)i * HH + tid];
    int d = g_cnt[i];
    if (d > CAP) d = CAP;
    if (tid < d) {
        sdst[tid] = g_bd[i * CAP + tid];
        ss[tid]   = g_bs[i * CAP + tid];
    }
    __syncthreads();

    // scores: one warp per entry, 128-dim dot over smem Q and L2 K
    for (int j = wid; j < d; j += 4) {
        int dj = sdst[j];
        float4 kv = ((const float4*)(g_K + (size_t)dj * HH))[lane];
        float4 qv = ((const float4*)qrow)[lane];
        float p = kv.x * qv.x + kv.y * qv.y + kv.z * qv.z + kv.w * qv.w;
#pragma unroll
        for (int off = 16; off; off >>= 1) p += __shfl_down_sync(0xffffffffu, p, off);
        if (lane == 0) {
            float s = p + ss[j];
            ss[j] = (s >= 0.f) ? s : 0.01f * s;   // leaky relu
        }
    }
    __syncthreads();

    // dedup: duplicate (i,dst) scores sum inside the exp; leader = lowest index
    if (tid < d) {
        int dj = sdst[tid];
        float s = 0.f;
        bool lead = true;
        for (int t = 0; t < d; t++) {
            if (sdst[t] == dj) {
                if (t < tid) { lead = false; break; }
                s += ss[t];
            }
        }
        sw[tid] = lead ? (expf(s) - 1.0f) : 0.0f;
    }
    __syncthreads();

    float acc = 0.f, wsum = 0.f;
    for (int t = 0; t < d; t++) {
        float w = sw[t];
        if (w != 0.f) {
            acc += w * g_V[(size_t)sdst[t] * HH + tid];
            wsum += w;
        }
    }
    float Z = (float)NN + wsum;
    float xn = (g_sv[tid] + acc) / Z;
    g_h1[(size_t)i * HH + tid] = x[(size_t)i * HH + tid] + xn;
}

// ---------------- final bn2 apply ----------------
__global__ void k_apply(float* __restrict__ out) {
    int t = blockIdx.x * 256 + threadIdx.x;
    int h = t & 127;
    out[t] = g_y[t] * g_a2[h] + g_c2[h];
}

// ---------------- launch ----------------
extern "C" void kernel_launch(void* const* d_in, const int* in_sizes, int n_in,
                              void* d_out, int out_size) {
    (void)in_sizes; (void)n_in; (void)out_size;
    const float* x   = (const float*)d_in[0];
    const void*  ei  = d_in[1];
    const float* ea  = (const float*)d_in[2];
    const float* Wq  = (const float*)d_in[3];
    const float* bq  = (const float*)d_in[4];
    const float* Wk  = (const float*)d_in[5];
    const float* bk  = (const float*)d_in[6];
    const float* Wv  = (const float*)d_in[7];
    const float* bv  = (const float*)d_in[8];
    const float* We  = (const float*)d_in[9];
    const float* be  = (const float*)d_in[10];
    const float* bn1g = (const float*)d_in[11];
    const float* bn1b = (const float*)d_in[12];
    const float* W1  = (const float*)d_in[13];
    const float* b1  = (const float*)d_in[14];
    const float* W2  = (const float*)d_in[15];
    const float* b2  = (const float*)d_in[16];
    const float* bn2g = (const float*)d_in[17];
    const float* bn2b = (const float*)d_in[18];
    float* out = (float*)d_out;

    float *pQ, *pK, *pV, *ph1, *pt1, *py, *pw1t, *pb1t;
    cudaGetSymbolAddress((void**)&pQ,   g_Q);
    cudaGetSymbolAddress((void**)&pK,   g_K);
    cudaGetSymbolAddress((void**)&pV,   g_V);
    cudaGetSymbolAddress((void**)&ph1,  g_h1);
    cudaGetSymbolAddress((void**)&pt1,  g_t1);
    cudaGetSymbolAddress((void**)&py,   g_y);
    cudaGetSymbolAddress((void**)&pw1t, g_w1t);
    cudaGetSymbolAddress((void**)&pb1t, g_b1t);

    const int SMEM = (2 * 64 * 36 + 2 * 32 * 132) * 4;   // 52224 B
    static int attrSet = 0;
    if (!attrSet) {
        cudaFuncSetAttribute(k_mm, cudaFuncAttributeMaxDynamicSharedMemorySize, SMEM);
        attrSet = 1;
    }

    k_init<<<64, 256>>>(ei);
    k_scatter<<<EE / 256, 256>>>(ei, ea, We, be);

    // fused QKV (z: 0=Q, 1=K, 2=V); V blocks also accumulate g_sv
    dim3 gqkv(1, NN / 64, 3);
    k_mm<<<gqkv, 256, SMEM>>>(x, Wq, Wk, Wv, bq, bk, bv, pQ, pK, pV,
                              HH, HH, 0, 0, 2, 0, bn2g, bn2b);

    k_rows<<<NN, 128>>>(x);

    k_cr1<<<128, 512>>>(ph1, bn1g, bn1b);   // bn1 stats + a1/c1 finalize
    k_prep1<<<256, 128>>>(W1, b1);

    // FFN1: [NN,128] @ folded [128,256], relu
    dim3 gf1(2 * HH / 128, NN / 64, 1);
    k_mm<<<gf1, 256, SMEM>>>(ph1, pw1t, pw1t, pw1t, pb1t, pb1t, pb1t,
                             pt1, pt1, pt1, HH, 2 * HH, 1, 0, -1, 0, bn2g, bn2b);
    // FFN2: [NN,256] @ [256,128] + bn1(h1) residual; blocks accumulate bn2 stats + finalize
    dim3 gf2(HH / 128, NN / 64, 1);
    k_mm<<<gf2, 256, SMEM>>>(pt1, W2, W2, W2, b2, b2, b2,
                             py, py, py, 2 * HH, HH, 0, 1, 0, 2, bn2g, bn2b);

    k_apply<<<NN * HH / 256, 256>>>(out);
}